// round 4
// baseline (speedup 1.0000x reference)
#include <cuda_runtime.h>
#include <cuda_bf16.h>
#include <mma.h>

using namespace nvcuda;

// Problem constants
constexpr int B = 32;
constexpr int L = 1024;
constexpr int D = 512;
constexpr float NEG_INF = -1000000000.0f;
constexpr float SCALE = 0.04419417382415922f; // 1/sqrt(512)

// Scratch for projected Q / K (fp32, row-major (B*L, D)).
// __device__ globals are the allocation-guard-legal scratch mechanism.
__device__ float g_Q[B * L * D];
__device__ float g_K[B * L * D];

// ---------------------------------------------------------------------------
// Projection: out = relu(in @ W + bias)
//   in  : (B*L, D) row-major,  W : (D, D) row-major,  out : (B*L, D)
// CTA = 64x64 output tile, 256 threads, wmma m16n16k8 TF32.
// ---------------------------------------------------------------------------
template <bool TO_Q>
__global__ void proj_kernel(const float* __restrict__ in,
                            const float* __restrict__ W,
                            const float* __restrict__ bias) {
    constexpr int TM = 64, TN = 64, TK = 32;
    __shared__ __align__(16) float As[TM][TK + 4];   // ld 36
    __shared__ __align__(16) float Bs[TK][TN + 4];   // ld 68
    __shared__ __align__(16) float Cs[TM][TN + 4];   // ld 68

    float* out = TO_Q ? g_Q : g_K;

    const int tid  = threadIdx.x;
    const int warp = tid >> 5;
    const int m0 = blockIdx.y * TM;
    const int n0 = blockIdx.x * TN;

    const int tr  = warp >> 1;          // 0..3
    const int tcb = (warp & 1) * 2;     // 0 or 2

    wmma::fragment<wmma::accumulator, 16, 16, 8, float> acc[2];
    wmma::fill_fragment(acc[0], 0.0f);
    wmma::fill_fragment(acc[1], 0.0f);

    for (int kt = 0; kt < D / TK; kt++) {
        const int k0 = kt * TK;
        // A tile: 64x32, vectorized (512 float4, 256 threads -> 2 each)
        for (int i = tid; i < TM * TK / 4; i += 256) {
            int idx = i << 2;
            int r = idx >> 5, c = idx & 31;
            *(float4*)&As[r][c] =
                *(const float4*)&in[(size_t)(m0 + r) * D + k0 + c];
        }
        // B tile: 32x64
        for (int i = tid; i < TK * TN / 4; i += 256) {
            int idx = i << 2;
            int r = idx >> 6, c = idx & 63;
            *(float4*)&Bs[r][c] =
                *(const float4*)&W[(size_t)(k0 + r) * D + n0 + c];
        }
        __syncthreads();

        #pragma unroll
        for (int k8 = 0; k8 < TK / 8; k8++) {
            wmma::fragment<wmma::matrix_a, 16, 16, 8, wmma::precision::tf32, wmma::row_major> a;
            wmma::load_matrix_sync(a, &As[tr * 16][k8 * 8], TK + 4);
            #pragma unroll
            for (int t = 0; t < a.num_elements; t++) a.x[t] = wmma::__float_to_tf32(a.x[t]);
            #pragma unroll
            for (int j = 0; j < 2; j++) {
                wmma::fragment<wmma::matrix_b, 16, 16, 8, wmma::precision::tf32, wmma::row_major> bf;
                wmma::load_matrix_sync(bf, &Bs[k8 * 8][(tcb + j) * 16], TN + 4);
                #pragma unroll
                for (int t = 0; t < bf.num_elements; t++) bf.x[t] = wmma::__float_to_tf32(bf.x[t]);
                wmma::mma_sync(acc[j], a, bf, acc[j]);
            }
        }
        __syncthreads();
    }

    wmma::store_matrix_sync(&Cs[tr * 16][tcb * 16],       acc[0], TN + 4, wmma::mem_row_major);
    wmma::store_matrix_sync(&Cs[tr * 16][(tcb + 1) * 16], acc[1], TN + 4, wmma::mem_row_major);
    __syncthreads();

    for (int i = tid; i < TM * TN / 4; i += 256) {
        int idx = i << 2;
        int r = idx >> 6, c = idx & 63;
        float4 v = *(const float4*)&Cs[r][c];
        v.x = fmaxf(v.x + bias[n0 + c + 0], 0.0f);
        v.y = fmaxf(v.y + bias[n0 + c + 1], 0.0f);
        v.z = fmaxf(v.z + bias[n0 + c + 2], 0.0f);
        v.w = fmaxf(v.w + bias[n0 + c + 3], 0.0f);
        *(float4*)&out[(size_t)(m0 + r) * D + n0 + c] = v;
    }
}

// ---------------------------------------------------------------------------
// Attention: per-CTA 32-query tile x full 1024 keys of one batch.
//   S = Q K^T  (wmma TF32, K streamed 128-key x 32-d chunks)
//   s = S*scale + keymask;  softmax over keys;  *= query_mask
// 512 threads (16 warps), one 16x16 S subtile per warp per key chunk.
// ---------------------------------------------------------------------------
constexpr int QT  = 32;        // query rows per CTA
constexpr int NT  = 128;       // keys per S subtile chunk
constexpr int DKC = 32;        // d-chunk
constexpr int LDQ = D + 4;     // 516
constexpr int LDS = L + 4;     // 1028
constexpr int LDK = DKC + 4;   // 36
constexpr int NTHREADS = 512;

constexpr int SM_Q = QT * LDQ;                     // 16512 floats
constexpr int SM_K = NT * LDK;                     // 4608 floats
constexpr int SM_S = QT * LDS;                     // 32896 floats
constexpr int SMEM_ATTN_BYTES = (SM_Q + SM_K + SM_S) * 4 + L * 4;  // 220160 B

__global__ __launch_bounds__(NTHREADS, 1)
void attn_kernel(const int* __restrict__ query_mask,
                 const int* __restrict__ key_mask,
                 float* __restrict__ out) {
    extern __shared__ __align__(128) float smem[];
    float* Qs = smem;
    float* Ks = Qs + SM_Q;
    float* Ss = Ks + SM_K;
    int*   kms = (int*)(Ss + SM_S);

    const int tid  = threadIdx.x;
    const int lane = tid & 31;
    const int warp = tid >> 5;                 // 0..15
    const int b  = blockIdx.y;
    const int q0 = blockIdx.x * QT;

    // Stage Q tile (32 x 512) vectorized: 4096 float4, 512 threads -> 8 each
    const float* Qg = g_Q + ((size_t)b * L + q0) * D;
    for (int i = tid; i < QT * D / 4; i += NTHREADS) {
        int idx = i << 2;
        int r = idx >> 9, c = idx & 511;
        *(float4*)&Qs[r * LDQ + c] = ((const float4*)Qg)[i];
    }
    for (int i = tid; i < L; i += NTHREADS) kms[i] = key_mask[(size_t)b * L + i];
    __syncthreads();

    // 2x8 grid of 16x16 S subtiles per chunk, one per warp
    const int tr = warp >> 3;                  // 0..1 (query subrow)
    const int tc = warp & 7;                   // 0..7 (key subcol)

    for (int nt = 0; nt < L / NT; nt++) {
        wmma::fragment<wmma::accumulator, 16, 16, 8, float> acc;
        wmma::fill_fragment(acc, 0.0f);

        const float* Kg = g_K + ((size_t)b * L + nt * NT) * D;
        for (int dk = 0; dk < D / DKC; dk++) {
            // Stage K chunk 128 x 32 vectorized (1024 float4 -> 2 each)
            for (int i = tid; i < NT * DKC / 4; i += NTHREADS) {
                int idx = i << 2;
                int kr = idx >> 5, kc = idx & 31;
                *(float4*)&Ks[kr * LDK + kc] =
                    *(const float4*)&Kg[(size_t)kr * D + dk * DKC + kc];
            }
            __syncthreads();

            #pragma unroll
            for (int k8 = 0; k8 < DKC / 8; k8++) {
                wmma::fragment<wmma::matrix_a, 16, 16, 8, wmma::precision::tf32, wmma::row_major> a;
                wmma::load_matrix_sync(a, &Qs[(tr * 16) * LDQ + dk * DKC + k8 * 8], LDQ);
                #pragma unroll
                for (int t = 0; t < a.num_elements; t++) a.x[t] = wmma::__float_to_tf32(a.x[t]);
                // B = K^T slice (8 d x 16 keys): col-major view of row-major K chunk
                wmma::fragment<wmma::matrix_b, 16, 16, 8, wmma::precision::tf32, wmma::col_major> bf;
                wmma::load_matrix_sync(bf, &Ks[(tc * 16) * LDK + k8 * 8], LDK);
                #pragma unroll
                for (int t = 0; t < bf.num_elements; t++) bf.x[t] = wmma::__float_to_tf32(bf.x[t]);
                wmma::mma_sync(acc, a, bf, acc);
            }
            __syncthreads();
        }
        wmma::store_matrix_sync(&Ss[(tr * 16) * LDS + nt * NT + tc * 16],
                                acc, LDS, wmma::mem_row_major);
    }
    __syncthreads();

    // Softmax: warp w owns rows 2w, 2w+1; 32 lanes cooperate per row
    for (int rr = 0; rr < 2; rr++) {
        const int r = warp * 2 + rr;
        float* srow = Ss + r * LDS;

        float mx = -3.4e38f;
        for (int c = lane; c < L; c += 32) {
            float s = srow[c] * SCALE + (kms[c] ? 0.0f : NEG_INF);
            mx = fmaxf(mx, s);
        }
        #pragma unroll
        for (int o = 16; o > 0; o >>= 1) mx = fmaxf(mx, __shfl_xor_sync(0xffffffffu, mx, o));

        float sum = 0.0f;
        for (int c = lane; c < L; c += 32) {
            float s = srow[c] * SCALE + (kms[c] ? 0.0f : NEG_INF);
            float e = __expf(s - mx);
            srow[c] = e;
            sum += e;
        }
        #pragma unroll
        for (int o = 16; o > 0; o >>= 1) sum += __shfl_xor_sync(0xffffffffu, sum, o);

        const float qm  = (float)query_mask[(size_t)b * L + q0 + r];
        const float inv = qm / sum;  // sum >= 1 (max element contributes exp(0)=1)

        float* orow = out + ((size_t)b * L + q0 + r) * L;
        for (int c4 = lane; c4 < L / 4; c4 += 32) {
            float4 v = *(const float4*)&srow[c4 << 2];
            v.x *= inv; v.y *= inv; v.z *= inv; v.w *= inv;
            ((float4*)orow)[c4] = v;
        }
    }
}

// ---------------------------------------------------------------------------
// kernel_launch — graph-capturable, allocation-free
// ---------------------------------------------------------------------------
extern "C" void kernel_launch(void* const* d_in, const int* in_sizes, int n_in,
                              void* d_out, int out_size) {
    (void)in_sizes; (void)n_in; (void)out_size;
    const float* query = (const float*)d_in[0];
    const float* key   = (const float*)d_in[1];
    const int*   qmask = (const int*)d_in[2];
    const int*   kmask = (const int*)d_in[3];
    const float* Wq    = (const float*)d_in[4];
    const float* bq    = (const float*)d_in[5];
    const float* Wk    = (const float*)d_in[6];
    const float* bk    = (const float*)d_in[7];
    float* out = (float*)d_out;

    static bool attr_set = false;
    if (!attr_set) {
        cudaFuncSetAttribute(attn_kernel,
                             cudaFuncAttributeMaxDynamicSharedMemorySize,
                             SMEM_ATTN_BYTES);
        attr_set = true;
    }

    dim3 pgrid(D / 64, (B * L) / 64);  // (8, 512)
    proj_kernel<true ><<<pgrid, 256>>>(query, Wq, bq);
    proj_kernel<false><<<pgrid, 256>>>(key,   Wk, bk);

    attn_kernel<<<dim3(L / QT, B), NTHREADS, SMEM_ATTN_BYTES>>>(qmask, kmask, out);
}

// round 5
// speedup vs baseline: 1.4873x; 1.4873x over previous
#include <cuda_runtime.h>
#include <cuda_bf16.h>
#include <mma.h>

using namespace nvcuda;

// Problem constants
constexpr int B = 32;
constexpr int L = 1024;
constexpr int D = 512;
constexpr float NEG_INF = -1000000000.0f;
constexpr float SCALE = 0.04419417382415922f; // 1/sqrt(512)

// Scratch for projected Q / K (fp32, row-major (B*L, D)).
__device__ float g_Q[B * L * D];
__device__ float g_K[B * L * D];

__device__ __forceinline__ float tf32r(float x) { return wmma::__float_to_tf32(x); }

// ---------------------------------------------------------------------------
// Projection: out = relu(in @ W + bias)
// CTA = 128x128 tile, 256 threads (8 warps), warp = 32x64 subtile.
// TF32 rounding applied once at SMEM staging.
// ---------------------------------------------------------------------------
constexpr int P_LDA = 36;    // 32 + 4
constexpr int P_LDB = 132;   // 128 + 4
constexpr int P_SM_A = 128 * P_LDA;           // 4608 floats
constexpr int P_SM_B = 32 * P_LDB;            // 4224 floats
constexpr int P_SM_C = 128 * P_LDB;           // 16896 floats (overlays A+B)
constexpr int PROJ_SMEM_BYTES = P_SM_C * 4;   // 67584 B

template <bool TO_Q>
__global__ __launch_bounds__(256, 2)
void proj_kernel(const float* __restrict__ in,
                 const float* __restrict__ W,
                 const float* __restrict__ bias) {
    extern __shared__ __align__(128) float ps[];
    float* As = ps;                 // [128][36]
    float* Bs = ps + P_SM_A;        // [32][132]
    float* Cs = ps;                 // [128][132] overlay (epilogue)

    float* out = TO_Q ? g_Q : g_K;

    const int tid  = threadIdx.x;
    const int warp = tid >> 5;
    const int m0 = blockIdx.y * 128;
    const int n0 = blockIdx.x * 128;

    const int wr = (warp >> 1) * 32;   // warp row offset (0,32,64,96)
    const int wc = (warp & 1) * 64;    // warp col offset (0,64)

    wmma::fragment<wmma::accumulator, 16, 16, 8, float> acc[2][4];
    #pragma unroll
    for (int i = 0; i < 2; i++)
        #pragma unroll
        for (int j = 0; j < 4; j++)
            wmma::fill_fragment(acc[i][j], 0.0f);

    for (int kt = 0; kt < D / 32; kt++) {
        const int k0 = kt * 32;
        // Stage A tile 128x32 (1024 float4), tf32-rounded
        for (int i = tid; i < 128 * 32 / 4; i += 256) {
            int idx = i << 2;
            int r = idx >> 5, c = idx & 31;
            float4 v = *(const float4*)&in[(size_t)(m0 + r) * D + k0 + c];
            float* dst = &As[r * P_LDA + c];
            dst[0] = tf32r(v.x); dst[1] = tf32r(v.y);
            dst[2] = tf32r(v.z); dst[3] = tf32r(v.w);
        }
        // Stage B tile 32x128 (1024 float4), tf32-rounded
        for (int i = tid; i < 32 * 128 / 4; i += 256) {
            int idx = i << 2;
            int r = idx >> 7, c = idx & 127;
            float4 v = *(const float4*)&W[(size_t)(k0 + r) * D + n0 + c];
            float* dst = &Bs[r * P_LDB + c];
            dst[0] = tf32r(v.x); dst[1] = tf32r(v.y);
            dst[2] = tf32r(v.z); dst[3] = tf32r(v.w);
        }
        __syncthreads();

        #pragma unroll
        for (int k8 = 0; k8 < 4; k8++) {
            wmma::fragment<wmma::matrix_a, 16, 16, 8, wmma::precision::tf32, wmma::row_major> a[2];
            #pragma unroll
            for (int i = 0; i < 2; i++)
                wmma::load_matrix_sync(a[i], &As[(wr + i * 16) * P_LDA + k8 * 8], P_LDA);
            #pragma unroll
            for (int j = 0; j < 4; j++) {
                wmma::fragment<wmma::matrix_b, 16, 16, 8, wmma::precision::tf32, wmma::row_major> bf;
                wmma::load_matrix_sync(bf, &Bs[(k8 * 8) * P_LDB + wc + j * 16], P_LDB);
                #pragma unroll
                for (int i = 0; i < 2; i++)
                    wmma::mma_sync(acc[i][j], a[i], bf, acc[i][j]);
            }
        }
        __syncthreads();
    }

    // Epilogue: accs -> Cs (overlay) -> bias+relu -> global
    #pragma unroll
    for (int i = 0; i < 2; i++)
        #pragma unroll
        for (int j = 0; j < 4; j++)
            wmma::store_matrix_sync(&Cs[(wr + i * 16) * P_LDB + wc + j * 16],
                                    acc[i][j], P_LDB, wmma::mem_row_major);
    __syncthreads();

    for (int i = tid; i < 128 * 128 / 4; i += 256) {
        int idx = i << 2;
        int r = idx >> 7, c = idx & 127;
        float4 v = *(const float4*)&Cs[r * P_LDB + c];
        const float* bp = &bias[n0 + c];
        v.x = fmaxf(v.x + bp[0], 0.0f);
        v.y = fmaxf(v.y + bp[1], 0.0f);
        v.z = fmaxf(v.z + bp[2], 0.0f);
        v.w = fmaxf(v.w + bp[3], 0.0f);
        *(float4*)&out[(size_t)(m0 + r) * D + n0 + c] = v;
    }
}

// ---------------------------------------------------------------------------
// Attention: CTA = 32 queries x 1024 keys of one batch.
// 512 threads (16 warps), warp tile = 16 queries x 128 keys, S held in
// registers (8 acc frags) across the whole d-loop. K staged full-width
// (1024 x 32) per d-chunk. S + key-bias overlay Q/K SMEM for softmax.
// ---------------------------------------------------------------------------
constexpr int QT  = 32;
constexpr int DKC = 32;
constexpr int LDQ = D + 4;     // 516
constexpr int LDK = DKC + 4;   // 36
constexpr int LDS = L + 4;     // 1028
constexpr int NTHREADS = 512;

constexpr int SM_Q = QT * LDQ;        // 16512 floats
constexpr int SM_K = L * LDK;         // 36864 floats
constexpr int SM_S = QT * LDS;        // 32896 floats
constexpr int SMEM_ATTN_BYTES = (SM_Q + SM_K) * 4;   // 213504 B (S+kb overlay: 135680 B)

__global__ __launch_bounds__(NTHREADS, 1)
void attn_kernel(const int* __restrict__ query_mask,
                 const int* __restrict__ key_mask,
                 float* __restrict__ out) {
    extern __shared__ __align__(128) float smem[];
    float* Qs = smem;               // [32][516]
    float* Ks = smem + SM_Q;        // [1024][36]
    float* Ss = smem;               // [32][1028] overlay
    float* kb = smem + SM_S;        // [1024] key bias overlay

    const int tid  = threadIdx.x;
    const int lane = tid & 31;
    const int warp = tid >> 5;      // 0..15
    const int b  = blockIdx.y;
    const int q0 = blockIdx.x * QT;

    // Stage Q tile 32x512, tf32-rounded
    const float* Qg = g_Q + ((size_t)b * L + q0) * D;
    for (int i = tid; i < QT * D / 4; i += NTHREADS) {
        int idx = i << 2;
        int r = idx >> 9, c = idx & 511;
        float4 v = ((const float4*)Qg)[i];
        float* dst = &Qs[r * LDQ + c];
        dst[0] = tf32r(v.x); dst[1] = tf32r(v.y);
        dst[2] = tf32r(v.z); dst[3] = tf32r(v.w);
    }
    __syncthreads();

    const int tr = (warp >> 3) * 16;    // query sub-row: 0 or 16
    const int tc = (warp & 7) * 128;    // key block: 0..896

    wmma::fragment<wmma::accumulator, 16, 16, 8, float> acc[8];
    #pragma unroll
    for (int j = 0; j < 8; j++) wmma::fill_fragment(acc[j], 0.0f);

    const float* Kg = g_K + (size_t)b * L * D;
    for (int dk = 0; dk < D / DKC; dk++) {
        // Stage K chunk 1024x32 (8192 float4), tf32-rounded
        for (int i = tid; i < L * DKC / 4; i += NTHREADS) {
            int idx = i << 2;
            int kr = idx >> 5, kc = idx & 31;
            float4 v = *(const float4*)&Kg[(size_t)kr * D + dk * DKC + kc];
            float* dst = &Ks[kr * LDK + kc];
            dst[0] = tf32r(v.x); dst[1] = tf32r(v.y);
            dst[2] = tf32r(v.z); dst[3] = tf32r(v.w);
        }
        __syncthreads();

        #pragma unroll
        for (int k8 = 0; k8 < DKC / 8; k8++) {
            wmma::fragment<wmma::matrix_a, 16, 16, 8, wmma::precision::tf32, wmma::row_major> a;
            wmma::load_matrix_sync(a, &Qs[tr * LDQ + dk * DKC + k8 * 8], LDQ);
            #pragma unroll
            for (int j = 0; j < 8; j++) {
                // B = K^T slice (8 d x 16 keys): col-major view of row-major K
                wmma::fragment<wmma::matrix_b, 16, 16, 8, wmma::precision::tf32, wmma::col_major> bf;
                wmma::load_matrix_sync(bf, &Ks[(tc + j * 16) * LDK + k8 * 8], LDK);
                wmma::mma_sync(acc[j], a, bf, acc[j]);
            }
        }
        __syncthreads();
    }

    // Store S into overlay SMEM (all Q/K reads complete after last sync)
    #pragma unroll
    for (int j = 0; j < 8; j++)
        wmma::store_matrix_sync(&Ss[tr * LDS + tc + j * 16], acc[j], LDS,
                                wmma::mem_row_major);
    // Key-mask bias (region beyond Ss, inside old Ks tail)
    for (int i = tid; i < L; i += NTHREADS)
        kb[i] = key_mask[(size_t)b * L + i] ? 0.0f : NEG_INF;
    __syncthreads();

    // Softmax: warp w owns rows 2w, 2w+1; 32 lanes cooperate per row
    #pragma unroll
    for (int rr = 0; rr < 2; rr++) {
        const int r = warp * 2 + rr;
        float* srow = Ss + r * LDS;

        float mx = -3.4e38f;
        for (int c = lane; c < L; c += 32)
            mx = fmaxf(mx, fmaf(srow[c], SCALE, kb[c]));
        #pragma unroll
        for (int o = 16; o > 0; o >>= 1) mx = fmaxf(mx, __shfl_xor_sync(0xffffffffu, mx, o));

        float sum = 0.0f;
        for (int c = lane; c < L; c += 32) {
            float e = __expf(fmaf(srow[c], SCALE, kb[c]) - mx);
            srow[c] = e;
            sum += e;
        }
        #pragma unroll
        for (int o = 16; o > 0; o >>= 1) sum += __shfl_xor_sync(0xffffffffu, sum, o);

        const float qm  = (float)query_mask[(size_t)b * L + q0 + r];
        const float inv = qm / sum;   // sum >= 1 (max element contributes exp(0)=1)

        float* orow = out + ((size_t)b * L + q0 + r) * L;
        for (int c4 = lane; c4 < L / 4; c4 += 32) {
            float4 v = *(const float4*)&srow[c4 << 2];
            v.x *= inv; v.y *= inv; v.z *= inv; v.w *= inv;
            ((float4*)orow)[c4] = v;
        }
    }
}

// ---------------------------------------------------------------------------
// kernel_launch — graph-capturable, allocation-free
// ---------------------------------------------------------------------------
extern "C" void kernel_launch(void* const* d_in, const int* in_sizes, int n_in,
                              void* d_out, int out_size) {
    (void)in_sizes; (void)n_in; (void)out_size;
    const float* query = (const float*)d_in[0];
    const float* key   = (const float*)d_in[1];
    const int*   qmask = (const int*)d_in[2];
    const int*   kmask = (const int*)d_in[3];
    const float* Wq    = (const float*)d_in[4];
    const float* bq    = (const float*)d_in[5];
    const float* Wk    = (const float*)d_in[6];
    const float* bk    = (const float*)d_in[7];
    float* out = (float*)d_out;

    static bool attr_set = false;
    if (!attr_set) {
        cudaFuncSetAttribute(proj_kernel<true>,
                             cudaFuncAttributeMaxDynamicSharedMemorySize, PROJ_SMEM_BYTES);
        cudaFuncSetAttribute(proj_kernel<false>,
                             cudaFuncAttributeMaxDynamicSharedMemorySize, PROJ_SMEM_BYTES);
        cudaFuncSetAttribute(attn_kernel,
                             cudaFuncAttributeMaxDynamicSharedMemorySize, SMEM_ATTN_BYTES);
        attr_set = true;
    }

    dim3 pgrid(D / 128, (B * L) / 128);  // (4, 256)
    proj_kernel<true ><<<pgrid, 256, PROJ_SMEM_BYTES>>>(query, Wq, bq);
    proj_kernel<false><<<pgrid, 256, PROJ_SMEM_BYTES>>>(key,   Wk, bk);

    attn_kernel<<<dim3(L / QT, B), NTHREADS, SMEM_ATTN_BYTES>>>(qmask, kmask, out);
}

// round 8
// speedup vs baseline: 2.3506x; 1.5805x over previous
#include <cuda_runtime.h>
#include <cuda_bf16.h>
#include <mma.h>
#include <cstdint>

using namespace nvcuda;

// Problem constants
constexpr int B = 32;
constexpr int L = 1024;
constexpr int D = 512;
constexpr float NEG_INF = -1000000000.0f;
constexpr float SCALE = 0.04419417382415922f; // 1/sqrt(512)

// __device__ scratch (allocation-guard-legal)
__device__ float g_Qr[B * L * D];   // tf32-rounded query input
__device__ float g_Kr[B * L * D];   // tf32-rounded key input
__device__ float g_Wqr[D * D];
__device__ float g_Wkr[D * D];
__device__ float g_Q[B * L * D];    // relu(q @ Wq + bq), tf32-rounded
__device__ float g_K[B * L * D];    // relu(k @ Wk + bk), tf32-rounded
__device__ float g_S[B * L * L];    // masked scaled logits

__device__ __forceinline__ float tf32r(float x) { return wmma::__float_to_tf32(x); }

// ---------------------------------------------------------------------------
// cp.async helpers
// ---------------------------------------------------------------------------
__device__ __forceinline__ void cp_async16(float* smem_dst, const float* gmem_src) {
    unsigned int s = (unsigned int)__cvta_generic_to_shared(smem_dst);
    asm volatile("cp.async.cg.shared.global [%0], [%1], 16;\n" :: "r"(s), "l"(gmem_src));
}
__device__ __forceinline__ void cp_commit() {
    asm volatile("cp.async.commit_group;\n");
}
template <int N>
__device__ __forceinline__ void cp_wait() {
    asm volatile("cp.async.wait_group %0;\n" :: "n"(N));
}

// ---------------------------------------------------------------------------
// round_kernel: dst = tf32_rn(src), grid-stride float4
// ---------------------------------------------------------------------------
__global__ __launch_bounds__(256)
void round_kernel(const float* __restrict__ src,
                  float* __restrict__ dst, int n4) {
    int i = blockIdx.x * blockDim.x + threadIdx.x;
    int stride = gridDim.x * blockDim.x;
    for (; i < n4; i += stride) {
        float4 v = ((const float4*)src)[i];
        v.x = tf32r(v.x); v.y = tf32r(v.y);
        v.z = tf32r(v.z); v.w = tf32r(v.w);
        ((float4*)dst)[i] = v;
    }
}

// ---------------------------------------------------------------------------
// proj: out = tf32_rn(relu(in @ W + bias))
// CTA 128x128, 256 threads (8 warps), warp 32x64. cp.async double buffer,
// TK=32. Inputs pre-rounded to tf32, so staging is a pure byte copy.
// ---------------------------------------------------------------------------
constexpr int P_LDA = 40;    // 32+8  (row = 160 B, 16B-aligned)
constexpr int P_LDB = 132;   // 128+4 (row = 528 B, 16B-aligned)
constexpr int P_A_SZ = 128 * P_LDA;   // 5120 floats per buffer
constexpr int P_B_SZ = 32 * P_LDB;    // 4224 floats per buffer
constexpr int PROJ_SMEM_BYTES = 2 * (P_A_SZ + P_B_SZ) * 4;  // 74752 B

template <bool TO_Q>
__global__ __launch_bounds__(256, 2)
void proj_kernel(const float* __restrict__ in,
                 const float* __restrict__ W,
                 const float* __restrict__ bias) {
    extern __shared__ __align__(128) float ps[];
    float* As[2] = { ps, ps + P_A_SZ };
    float* Bs[2] = { ps + 2 * P_A_SZ, ps + 2 * P_A_SZ + P_B_SZ };
    float* Cs = ps;  // [128][132] epilogue overlay (fenced by final sync)

    float* out = TO_Q ? g_Q : g_K;

    const int tid  = threadIdx.x;
    const int warp = tid >> 5;
    const int m0 = blockIdx.y * 128;
    const int n0 = blockIdx.x * 128;

    const int wr = (warp >> 1) * 32;
    const int wc = (warp & 1) * 64;

    const float* Ain = in + (size_t)m0 * D;

    auto stage = [&](int kt) {
        const int pb = kt & 1;
        const int k0 = kt * 32;
        #pragma unroll
        for (int i = 0; i < 4; i++) {          // A: 128x32 = 1024 float4
            int idx = (tid + i * 256) << 2;
            int r = idx >> 5, c = idx & 31;
            cp_async16(&As[pb][r * P_LDA + c], Ain + (size_t)r * D + k0 + c);
        }
        #pragma unroll
        for (int i = 0; i < 4; i++) {          // B: 32x128 = 1024 float4
            int idx = (tid + i * 256) << 2;
            int r = idx >> 7, c = idx & 127;
            cp_async16(&Bs[pb][r * P_LDB + c], W + (size_t)(k0 + r) * D + n0 + c);
        }
        cp_commit();
    };

    wmma::fragment<wmma::accumulator, 16, 16, 8, float> acc[2][4];
    #pragma unroll
    for (int i = 0; i < 2; i++)
        #pragma unroll
        for (int j = 0; j < 4; j++) wmma::fill_fragment(acc[i][j], 0.0f);

    stage(0);
    for (int kt = 0; kt < D / 32; kt++) {
        const int pb = kt & 1;
        if (kt < D / 32 - 1) { stage(kt + 1); cp_wait<1>(); }
        else                 { cp_wait<0>(); }
        __syncthreads();

        #pragma unroll
        for (int k8 = 0; k8 < 4; k8++) {
            wmma::fragment<wmma::matrix_a, 16, 16, 8, wmma::precision::tf32, wmma::row_major> a[2];
            #pragma unroll
            for (int i = 0; i < 2; i++)
                wmma::load_matrix_sync(a[i], &As[pb][(wr + i * 16) * P_LDA + k8 * 8], P_LDA);
            #pragma unroll
            for (int j = 0; j < 4; j++) {
                wmma::fragment<wmma::matrix_b, 16, 16, 8, wmma::precision::tf32, wmma::row_major> bf;
                wmma::load_matrix_sync(bf, &Bs[pb][(k8 * 8) * P_LDB + wc + j * 16], P_LDB);
                #pragma unroll
                for (int i = 0; i < 2; i++)
                    wmma::mma_sync(acc[i][j], a[i], bf, acc[i][j]);
            }
        }
        __syncthreads();
    }

    // Epilogue: accs -> Cs overlay -> bias + relu + tf32 round -> global
    #pragma unroll
    for (int i = 0; i < 2; i++)
        #pragma unroll
        for (int j = 0; j < 4; j++)
            wmma::store_matrix_sync(&Cs[(wr + i * 16) * P_LDB + wc + j * 16],
                                    acc[i][j], P_LDB, wmma::mem_row_major);
    __syncthreads();

    for (int i = tid; i < 128 * 128 / 4; i += 256) {
        int idx = i << 2;
        int r = idx >> 7, c = idx & 127;
        float4 v = *(const float4*)&Cs[r * P_LDB + c];
        const float* bp = &bias[n0 + c];
        v.x = tf32r(fmaxf(v.x + bp[0], 0.0f));
        v.y = tf32r(fmaxf(v.y + bp[1], 0.0f));
        v.z = tf32r(fmaxf(v.z + bp[2], 0.0f));
        v.w = tf32r(fmaxf(v.w + bp[3], 0.0f));
        *(float4*)&out[(size_t)(m0 + r) * D + n0 + c] = v;
    }
}

// ---------------------------------------------------------------------------
// logits: S[b, m, n] = (Q[b,m,:] . K[b,n,:]) * SCALE + (key_mask[b,n]?0:NEG)
// CTA 128 queries x 128 keys, 256 threads, warp 32x64, cp.async pipelined.
// Grid x/y inner, z = batch -> one batch's 64 CTAs share 4 MB Q/K in L2.
// ---------------------------------------------------------------------------
constexpr int G_LD = 40;              // 32+8
constexpr int G_T_SZ = 128 * G_LD;    // 5120 floats per tile buffer
constexpr int LOGITS_SMEM_BYTES = 4 * G_T_SZ * 4;  // 81920 B

__global__ __launch_bounds__(256, 2)
void logits_kernel(const int* __restrict__ key_mask) {
    extern __shared__ __align__(128) float ls[];
    float* Qs[2] = { ls, ls + G_T_SZ };
    float* Ks[2] = { ls + 2 * G_T_SZ, ls + 3 * G_T_SZ };
    float* Cs = ls;  // [128][132] overlay

    const int tid  = threadIdx.x;
    const int warp = tid >> 5;
    const int b  = blockIdx.z;
    const int m0 = blockIdx.y * 128;
    const int n0 = blockIdx.x * 128;

    const int wr = (warp >> 1) * 32;
    const int wc = (warp & 1) * 64;

    const float* Qg = g_Q + ((size_t)b * L + m0) * D;
    const float* Kg = g_K + ((size_t)b * L + n0) * D;

    auto stage = [&](int kt) {
        const int pb = kt & 1;
        const int k0 = kt * 32;
        #pragma unroll
        for (int i = 0; i < 4; i++) {
            int idx = (tid + i * 256) << 2;
            int r = idx >> 5, c = idx & 31;
            cp_async16(&Qs[pb][r * G_LD + c], Qg + (size_t)r * D + k0 + c);
        }
        #pragma unroll
        for (int i = 0; i < 4; i++) {
            int idx = (tid + i * 256) << 2;
            int r = idx >> 5, c = idx & 31;
            cp_async16(&Ks[pb][r * G_LD + c], Kg + (size_t)r * D + k0 + c);
        }
        cp_commit();
    };

    wmma::fragment<wmma::accumulator, 16, 16, 8, float> acc[2][4];
    #pragma unroll
    for (int i = 0; i < 2; i++)
        #pragma unroll
        for (int j = 0; j < 4; j++) wmma::fill_fragment(acc[i][j], 0.0f);

    stage(0);
    for (int kt = 0; kt < D / 32; kt++) {
        const int pb = kt & 1;
        if (kt < D / 32 - 1) { stage(kt + 1); cp_wait<1>(); }
        else                 { cp_wait<0>(); }
        __syncthreads();

        #pragma unroll
        for (int k8 = 0; k8 < 4; k8++) {
            wmma::fragment<wmma::matrix_a, 16, 16, 8, wmma::precision::tf32, wmma::row_major> a[2];
            #pragma unroll
            for (int i = 0; i < 2; i++)
                wmma::load_matrix_sync(a[i], &Qs[pb][(wr + i * 16) * G_LD + k8 * 8], G_LD);
            #pragma unroll
            for (int j = 0; j < 4; j++) {
                // B = K^T slice: col-major view of row-major K tile
                wmma::fragment<wmma::matrix_b, 16, 16, 8, wmma::precision::tf32, wmma::col_major> bf;
                wmma::load_matrix_sync(bf, &Ks[pb][(wc + j * 16) * G_LD + k8 * 8], G_LD);
                #pragma unroll
                for (int i = 0; i < 2; i++)
                    wmma::mma_sync(acc[i][j], a[i], bf, acc[i][j]);
            }
        }
        __syncthreads();
    }

    #pragma unroll
    for (int i = 0; i < 2; i++)
        #pragma unroll
        for (int j = 0; j < 4; j++)
            wmma::store_matrix_sync(&Cs[(wr + i * 16) * P_LDB + wc + j * 16],
                                    acc[i][j], P_LDB, wmma::mem_row_major);
    __syncthreads();

    // Epilogue: scale + key-mask bias -> g_S
    const int* kmrow = key_mask + (size_t)b * L + n0;
    for (int i = tid; i < 128 * 128 / 4; i += 256) {
        int idx = i << 2;
        int r = idx >> 7, c = idx & 127;
        float4 v = *(const float4*)&Cs[r * P_LDB + c];
        v.x = fmaf(v.x, SCALE, kmrow[c + 0] ? 0.0f : NEG_INF);
        v.y = fmaf(v.y, SCALE, kmrow[c + 1] ? 0.0f : NEG_INF);
        v.z = fmaf(v.z, SCALE, kmrow[c + 2] ? 0.0f : NEG_INF);
        v.w = fmaf(v.w, SCALE, kmrow[c + 3] ? 0.0f : NEG_INF);
        *(float4*)&g_S[((size_t)b * L + m0 + r) * L + n0 + c] = v;
    }
}

// ---------------------------------------------------------------------------
// softmax: per-row (1024 keys) register-resident softmax * query_mask
// 256 threads = 8 warps, 1 row per warp, 32 floats per lane.
// ---------------------------------------------------------------------------
__global__ __launch_bounds__(256)
void softmax_kernel(const int* __restrict__ query_mask,
                    float* __restrict__ out) {
    const int lane = threadIdx.x & 31;
    const int warp = threadIdx.x >> 5;
    const size_t row = (size_t)blockIdx.x * 8 + warp;

    const float4* srow = (const float4*)(g_S + row * L);
    float4 v[8];
    #pragma unroll
    for (int j = 0; j < 8; j++) v[j] = srow[lane + j * 32];

    float mx = -3.4e38f;
    #pragma unroll
    for (int j = 0; j < 8; j++)
        mx = fmaxf(mx, fmaxf(fmaxf(v[j].x, v[j].y), fmaxf(v[j].z, v[j].w)));
    #pragma unroll
    for (int o = 16; o > 0; o >>= 1) mx = fmaxf(mx, __shfl_xor_sync(0xffffffffu, mx, o));

    float sum = 0.0f;
    #pragma unroll
    for (int j = 0; j < 8; j++) {
        v[j].x = __expf(v[j].x - mx);
        v[j].y = __expf(v[j].y - mx);
        v[j].z = __expf(v[j].z - mx);
        v[j].w = __expf(v[j].w - mx);
        sum += (v[j].x + v[j].y) + (v[j].z + v[j].w);
    }
    #pragma unroll
    for (int o = 16; o > 0; o >>= 1) sum += __shfl_xor_sync(0xffffffffu, sum, o);

    const float inv = (float)query_mask[row] / sum;  // sum >= 1

    float4* orow = (float4*)(out + row * L);
    #pragma unroll
    for (int j = 0; j < 8; j++) {
        v[j].x *= inv; v[j].y *= inv; v[j].z *= inv; v[j].w *= inv;
        orow[lane + j * 32] = v[j];
    }
}

// ---------------------------------------------------------------------------
// kernel_launch — graph-capturable, allocation-free
// ---------------------------------------------------------------------------
extern "C" void kernel_launch(void* const* d_in, const int* in_sizes, int n_in,
                              void* d_out, int out_size) {
    (void)in_sizes; (void)n_in; (void)out_size;
    const float* query = (const float*)d_in[0];
    const float* key   = (const float*)d_in[1];
    const int*   qmask = (const int*)d_in[2];
    const int*   kmask = (const int*)d_in[3];
    const float* Wq    = (const float*)d_in[4];
    const float* bq    = (const float*)d_in[5];
    const float* Wk    = (const float*)d_in[6];
    const float* bk    = (const float*)d_in[7];
    float* out = (float*)d_out;

    static float *d_Qr = nullptr, *d_Kr, *d_Wqr, *d_Wkr;
    if (!d_Qr) {
        cudaFuncSetAttribute(proj_kernel<true>,
                             cudaFuncAttributeMaxDynamicSharedMemorySize, PROJ_SMEM_BYTES);
        cudaFuncSetAttribute(proj_kernel<false>,
                             cudaFuncAttributeMaxDynamicSharedMemorySize, PROJ_SMEM_BYTES);
        cudaFuncSetAttribute(logits_kernel,
                             cudaFuncAttributeMaxDynamicSharedMemorySize, LOGITS_SMEM_BYTES);
        cudaGetSymbolAddress((void**)&d_Kr,  g_Kr);
        cudaGetSymbolAddress((void**)&d_Wqr, g_Wqr);
        cudaGetSymbolAddress((void**)&d_Wkr, g_Wkr);
        cudaGetSymbolAddress((void**)&d_Qr,  g_Qr);  // last: guards the block
    }

    // 1) pre-round inputs to tf32 (RN)
    const int nQK4 = B * L * D / 4;   // 4,194,304
    const int nW4  = D * D / 4;       // 65,536
    round_kernel<<<1184, 256>>>(query, d_Qr, nQK4);
    round_kernel<<<1184, 256>>>(key,   d_Kr, nQK4);
    round_kernel<<<256,  256>>>(Wq,    d_Wqr, nW4);
    round_kernel<<<256,  256>>>(Wk,    d_Wkr, nW4);

    // 2) projections
    dim3 pgrid(D / 128, (B * L) / 128);  // (4, 256)
    proj_kernel<true ><<<pgrid, 256, PROJ_SMEM_BYTES>>>(d_Qr, d_Wqr, bq);
    proj_kernel<false><<<pgrid, 256, PROJ_SMEM_BYTES>>>(d_Kr, d_Wkr, bk);

    // 3) masked scaled logits
    logits_kernel<<<dim3(L / 128, L / 128, B), 256, LOGITS_SMEM_BYTES>>>(kmask);

    // 4) softmax + query mask
    softmax_kernel<<<(B * L) / 8, 256>>>(qmask, out);
}

// round 12
// speedup vs baseline: 7.5606x; 3.2165x over previous
#include <cuda_runtime.h>
#include <cuda_fp16.h>
#include <mma.h>
#include <cstdint>

using namespace nvcuda;

// Problem constants
constexpr int B = 32;
constexpr int L = 1024;
constexpr int D = 512;
constexpr float NEG_INF = -1000000000.0f;
constexpr float SCALE = 0.04419417382415922f; // 1/sqrt(512)

// __device__ scratch (allocation-guard-legal)
__device__ __half g_Qh[B * L * D];   // half-rounded query input
__device__ __half g_Kh[B * L * D];   // half-rounded key input
__device__ __half g_Wqh[D * D];      // half-rounded Wq
__device__ __half g_Wkh[D * D];      // half-rounded Wk
__device__ __half g_Q[B * L * D];    // relu(q@Wq+bq), half
__device__ __half g_K[B * L * D];    // relu(k@Wk+bk), half
__device__ float  g_S[B * L * L];    // masked scaled logits (fp32)

// ---------------------------------------------------------------------------
// cp.async helpers
// ---------------------------------------------------------------------------
__device__ __forceinline__ void cp_async16(void* smem_dst, const void* gmem_src) {
    unsigned int s = (unsigned int)__cvta_generic_to_shared(smem_dst);
    asm volatile("cp.async.cg.shared.global [%0], [%1], 16;\n" :: "r"(s), "l"(gmem_src));
}
__device__ __forceinline__ void cp_commit() {
    asm volatile("cp.async.commit_group;\n");
}
template <int N>
__device__ __forceinline__ void cp_wait() {
    asm volatile("cp.async.wait_group %0;\n" :: "n"(N));
}

// ---------------------------------------------------------------------------
// round_half: dst = half_rn(src), 8 floats -> 8 halfs (16B store) per iter
// ---------------------------------------------------------------------------
__global__ __launch_bounds__(256)
void round_half(const float* __restrict__ src, __half* __restrict__ dst, int n8) {
    int i = blockIdx.x * blockDim.x + threadIdx.x;
    int stride = gridDim.x * blockDim.x;
    for (; i < n8; i += stride) {
        float4 a = ((const float4*)src)[2 * i];
        float4 b = ((const float4*)src)[2 * i + 1];
        __half2 h0 = __floats2half2_rn(a.x, a.y);
        __half2 h1 = __floats2half2_rn(a.z, a.w);
        __half2 h2 = __floats2half2_rn(b.x, b.y);
        __half2 h3 = __floats2half2_rn(b.z, b.w);
        uint4 o;
        o.x = *(unsigned int*)&h0; o.y = *(unsigned int*)&h1;
        o.z = *(unsigned int*)&h2; o.w = *(unsigned int*)&h3;
        ((uint4*)dst)[i] = o;
    }
}

// ---------------------------------------------------------------------------
// proj: out = half_rn(relu(in @ W + bias))
// CTA 128x128, 256 threads (8 warps), warp 32x64, fp16 wmma m16n16k16.
// cp.async double buffer, TK=32 halfs (2 k16-steps per chunk).
// SMEM (halfs): As0@0, As1@5120 (128x40), Bs0@10240, Bs1@14592 (32x136);
// epilogue Cs f32 128x132 overlays everything. SMEM = 67584 B, 2 CTAs/SM.
// ---------------------------------------------------------------------------
constexpr int GEMM_SMEM_BYTES = 128 * 132 * 4;  // 67584

template <bool TO_Q>
__global__ __launch_bounds__(256, 2)
void proj_kernel(const __half* __restrict__ in,
                 const __half* __restrict__ W,
                 const float* __restrict__ bias) {
    extern __shared__ __align__(128) char smem_raw[];
    __half* smh = (__half*)smem_raw;
    float*  Cs  = (float*)smem_raw;   // epilogue overlay

    __half* out = TO_Q ? g_Q : g_K;

    const int tid  = threadIdx.x;
    const int warp = tid >> 5;
    const int m0 = blockIdx.y * 128;
    const int n0 = blockIdx.x * 128;

    const int wr = (warp >> 1) * 32;   // 0,32,64,96
    const int wc = (warp & 1) * 64;    // 0,64

    const __half* Ain = in + (size_t)m0 * D;

    auto stage = [&](int kt) {
        const int pb = kt & 1;
        const int k0 = kt * 32;
        __half* Ab = smh + pb * 5120;           // 128 x ld40
        __half* Bb = smh + 10240 + pb * 4352;   // 32 x ld136
        #pragma unroll
        for (int i = 0; i < 2; i++) {           // A: 512 chunks of 8 halfs
            int idx = tid + i * 256;
            int r = idx >> 2, c8 = (idx & 3) << 3;
            cp_async16(&Ab[r * 40 + c8], Ain + (size_t)r * D + k0 + c8);
        }
        #pragma unroll
        for (int i = 0; i < 2; i++) {           // B: 512 chunks
            int idx = tid + i * 256;
            int r = idx >> 4, c8 = (idx & 15) << 3;
            cp_async16(&Bb[r * 136 + c8], W + (size_t)(k0 + r) * D + n0 + c8);
        }
        cp_commit();
    };

    wmma::fragment<wmma::accumulator, 16, 16, 16, float> acc[2][4];
    #pragma unroll
    for (int i = 0; i < 2; i++)
        #pragma unroll
        for (int j = 0; j < 4; j++) wmma::fill_fragment(acc[i][j], 0.0f);

    stage(0);
    for (int kt = 0; kt < 16; kt++) {
        const int pb = kt & 1;
        if (kt < 15) { stage(kt + 1); cp_wait<1>(); }
        else         { cp_wait<0>(); }
        __syncthreads();

        const __half* Ab = smh + pb * 5120;
        const __half* Bb = smh + 10240 + pb * 4352;
        #pragma unroll
        for (int k16 = 0; k16 < 2; k16++) {
            wmma::fragment<wmma::matrix_a, 16, 16, 16, __half, wmma::row_major> a[2];
            #pragma unroll
            for (int i = 0; i < 2; i++)
                wmma::load_matrix_sync(a[i], &Ab[(wr + i * 16) * 40 + k16 * 16], 40);
            #pragma unroll
            for (int j = 0; j < 4; j++) {
                wmma::fragment<wmma::matrix_b, 16, 16, 16, __half, wmma::row_major> bf;
                wmma::load_matrix_sync(bf, &Bb[(k16 * 16) * 136 + wc + j * 16], 136);
                #pragma unroll
                for (int i = 0; i < 2; i++)
                    wmma::mma_sync(acc[i][j], a[i], bf, acc[i][j]);
            }
        }
        __syncthreads();
    }

    // Epilogue: accs -> Cs (f32 overlay) -> bias+relu -> half -> global
    #pragma unroll
    for (int i = 0; i < 2; i++)
        #pragma unroll
        for (int j = 0; j < 4; j++)
            wmma::store_matrix_sync(&Cs[(wr + i * 16) * 132 + wc + j * 16],
                                    acc[i][j], 132, wmma::mem_row_major);
    __syncthreads();

    for (int i = tid; i < 128 * 128 / 8; i += 256) {
        int idx = i << 3;
        int r = idx >> 7, c = idx & 127;
        float4 v0 = *(const float4*)&Cs[r * 132 + c];
        float4 v1 = *(const float4*)&Cs[r * 132 + c + 4];
        const float* bp = &bias[n0 + c];
        __half2 h0 = __floats2half2_rn(fmaxf(v0.x + bp[0], 0.0f), fmaxf(v0.y + bp[1], 0.0f));
        __half2 h1 = __floats2half2_rn(fmaxf(v0.z + bp[2], 0.0f), fmaxf(v0.w + bp[3], 0.0f));
        __half2 h2 = __floats2half2_rn(fmaxf(v1.x + bp[4], 0.0f), fmaxf(v1.y + bp[5], 0.0f));
        __half2 h3 = __floats2half2_rn(fmaxf(v1.z + bp[6], 0.0f), fmaxf(v1.w + bp[7], 0.0f));
        uint4 o;
        o.x = *(unsigned int*)&h0; o.y = *(unsigned int*)&h1;
        o.z = *(unsigned int*)&h2; o.w = *(unsigned int*)&h3;
        *(uint4*)&out[(size_t)(m0 + r) * D + n0 + c] = o;
    }
}

// ---------------------------------------------------------------------------
// logits: S[b,m,n] = (Q[b,m,:].K[b,n,:])*SCALE + (key_mask[b,n]?0:NEG)
// CTA 128 queries x 128 keys, 256 threads, warp 32x64, fp16 wmma.
// K^T realized as col_major b-fragment over row-major K tile.
// SMEM (halfs): Qs0@0, Qs1@5120, Ks0@10240, Ks1@15360 (all 128x40);
// epilogue Cs f32 overlays. Grid (8,8,32): batch outer for L2 reuse.
// ---------------------------------------------------------------------------
__global__ __launch_bounds__(256, 2)
void logits_kernel(const int* __restrict__ key_mask) {
    extern __shared__ __align__(128) char smem_raw[];
    __half* smh = (__half*)smem_raw;
    float*  Cs  = (float*)smem_raw;

    const int tid  = threadIdx.x;
    const int warp = tid >> 5;
    const int b  = blockIdx.z;
    const int m0 = blockIdx.y * 128;
    const int n0 = blockIdx.x * 128;

    const int wr = (warp >> 1) * 32;
    const int wc = (warp & 1) * 64;

    const __half* Qg = g_Q + ((size_t)b * L + m0) * D;
    const __half* Kg = g_K + ((size_t)b * L + n0) * D;

    auto stage = [&](int kt) {
        const int pb = kt & 1;
        const int k0 = kt * 32;
        __half* Qb = smh + pb * 5120;
        __half* Kb = smh + 10240 + pb * 5120;
        #pragma unroll
        for (int i = 0; i < 2; i++) {
            int idx = tid + i * 256;
            int r = idx >> 2, c8 = (idx & 3) << 3;
            cp_async16(&Qb[r * 40 + c8], Qg + (size_t)r * D + k0 + c8);
        }
        #pragma unroll
        for (int i = 0; i < 2; i++) {
            int idx = tid + i * 256;
            int r = idx >> 2, c8 = (idx & 3) << 3;
            cp_async16(&Kb[r * 40 + c8], Kg + (size_t)r * D + k0 + c8);
        }
        cp_commit();
    };

    wmma::fragment<wmma::accumulator, 16, 16, 16, float> acc[2][4];
    #pragma unroll
    for (int i = 0; i < 2; i++)
        #pragma unroll
        for (int j = 0; j < 4; j++) wmma::fill_fragment(acc[i][j], 0.0f);

    stage(0);
    for (int kt = 0; kt < 16; kt++) {
        const int pb = kt & 1;
        if (kt < 15) { stage(kt + 1); cp_wait<1>(); }
        else         { cp_wait<0>(); }
        __syncthreads();

        const __half* Qb = smh + pb * 5120;
        const __half* Kb = smh + 10240 + pb * 5120;
        #pragma unroll
        for (int k16 = 0; k16 < 2; k16++) {
            wmma::fragment<wmma::matrix_a, 16, 16, 16, __half, wmma::row_major> a[2];
            #pragma unroll
            for (int i = 0; i < 2; i++)
                wmma::load_matrix_sync(a[i], &Qb[(wr + i * 16) * 40 + k16 * 16], 40);
            #pragma unroll
            for (int j = 0; j < 4; j++) {
                // B = K^T slice: col-major view of row-major K tile
                wmma::fragment<wmma::matrix_b, 16, 16, 16, __half, wmma::col_major> bf;
                wmma::load_matrix_sync(bf, &Kb[(wc + j * 16) * 40 + k16 * 16], 40);
                #pragma unroll
                for (int i = 0; i < 2; i++)
                    wmma::mma_sync(acc[i][j], a[i], bf, acc[i][j]);
            }
        }
        __syncthreads();
    }

    #pragma unroll
    for (int i = 0; i < 2; i++)
        #pragma unroll
        for (int j = 0; j < 4; j++)
            wmma::store_matrix_sync(&Cs[(wr + i * 16) * 132 + wc + j * 16],
                                    acc[i][j], 132, wmma::mem_row_major);
    __syncthreads();

    // Epilogue: scale + key-mask bias -> g_S (fp32)
    const int* km = key_mask + (size_t)b * L + n0;
    for (int i = tid; i < 128 * 128 / 4; i += 256) {
        int idx = i << 2;
        int r = idx >> 7, c = idx & 127;
        float4 v = *(const float4*)&Cs[r * 132 + c];
        v.x = fmaf(v.x, SCALE, km[c + 0] ? 0.0f : NEG_INF);
        v.y = fmaf(v.y, SCALE, km[c + 1] ? 0.0f : NEG_INF);
        v.z = fmaf(v.z, SCALE, km[c + 2] ? 0.0f : NEG_INF);
        v.w = fmaf(v.w, SCALE, km[c + 3] ? 0.0f : NEG_INF);
        *(float4*)&g_S[((size_t)b * L + m0 + r) * L + n0 + c] = v;
    }
}

// ---------------------------------------------------------------------------
// softmax: per-row (1024 keys) register-resident softmax * query_mask
// 256 threads = 8 warps, 1 row per warp, 32 floats per lane.
// ---------------------------------------------------------------------------
__global__ __launch_bounds__(256)
void softmax_kernel(const int* __restrict__ query_mask,
                    float* __restrict__ out) {
    const int lane = threadIdx.x & 31;
    const int warp = threadIdx.x >> 5;
    const size_t row = (size_t)blockIdx.x * 8 + warp;

    const float4* srow = (const float4*)(g_S + row * L);
    float4 v[8];
    #pragma unroll
    for (int j = 0; j < 8; j++) v[j] = srow[lane + j * 32];

    float mx = -3.4e38f;
    #pragma unroll
    for (int j = 0; j < 8; j++)
        mx = fmaxf(mx, fmaxf(fmaxf(v[j].x, v[j].y), fmaxf(v[j].z, v[j].w)));
    #pragma unroll
    for (int o = 16; o > 0; o >>= 1) mx = fmaxf(mx, __shfl_xor_sync(0xffffffffu, mx, o));

    float sum = 0.0f;
    #pragma unroll
    for (int j = 0; j < 8; j++) {
        v[j].x = __expf(v[j].x - mx);
        v[j].y = __expf(v[j].y - mx);
        v[j].z = __expf(v[j].z - mx);
        v[j].w = __expf(v[j].w - mx);
        sum += (v[j].x + v[j].y) + (v[j].z + v[j].w);
    }
    #pragma unroll
    for (int o = 16; o > 0; o >>= 1) sum += __shfl_xor_sync(0xffffffffu, sum, o);

    const float inv = (float)query_mask[row] / sum;  // sum >= 1

    float4* orow = (float4*)(out + row * L);
    #pragma unroll
    for (int j = 0; j < 8; j++) {
        v[j].x *= inv; v[j].y *= inv; v[j].z *= inv; v[j].w *= inv;
        orow[lane + j * 32] = v[j];
    }
}

// ---------------------------------------------------------------------------
// kernel_launch — graph-capturable, allocation-free
// ---------------------------------------------------------------------------
extern "C" void kernel_launch(void* const* d_in, const int* in_sizes, int n_in,
                              void* d_out, int out_size) {
    (void)in_sizes; (void)n_in; (void)out_size;
    const float* query = (const float*)d_in[0];
    const float* key   = (const float*)d_in[1];
    const int*   qmask = (const int*)d_in[2];
    const int*   kmask = (const int*)d_in[3];
    const float* Wq    = (const float*)d_in[4];
    const float* bq    = (const float*)d_in[5];
    const float* Wk    = (const float*)d_in[6];
    const float* bk    = (const float*)d_in[7];
    float* out = (float*)d_out;

    static __half *d_Qh = nullptr, *d_Kh, *d_Wqh, *d_Wkh;
    if (!d_Qh) {
        cudaFuncSetAttribute(proj_kernel<true>,
                             cudaFuncAttributeMaxDynamicSharedMemorySize, GEMM_SMEM_BYTES);
        cudaFuncSetAttribute(proj_kernel<false>,
                             cudaFuncAttributeMaxDynamicSharedMemorySize, GEMM_SMEM_BYTES);
        cudaFuncSetAttribute(logits_kernel,
                             cudaFuncAttributeMaxDynamicSharedMemorySize, GEMM_SMEM_BYTES);
        cudaGetSymbolAddress((void**)&d_Kh,  g_Kh);
        cudaGetSymbolAddress((void**)&d_Wqh, g_Wqh);
        cudaGetSymbolAddress((void**)&d_Wkh, g_Wkh);
        cudaGetSymbolAddress((void**)&d_Qh,  g_Qh);  // last: guards the block
    }

    // 1) round inputs + weights to fp16 (RN)
    const int nQK8 = B * L * D / 8;   // 2,097,152
    const int nW8  = D * D / 8;       // 32,768
    round_half<<<1184, 256>>>(query, d_Qh, nQK8);
    round_half<<<1184, 256>>>(key,   d_Kh, nQK8);
    round_half<<<128,  256>>>(Wq,    d_Wqh, nW8);
    round_half<<<128,  256>>>(Wk,    d_Wkh, nW8);

    // 2) projections
    dim3 pgrid(D / 128, (B * L) / 128);  // (4, 256)
    proj_kernel<true ><<<pgrid, 256, GEMM_SMEM_BYTES>>>(d_Qh, d_Wqh, bq);
    proj_kernel<false><<<pgrid, 256, GEMM_SMEM_BYTES>>>(d_Kh, d_Wkh, bk);

    // 3) masked scaled logits
    logits_kernel<<<dim3(L / 128, L / 128, B), 256, GEMM_SMEM_BYTES>>>(kmask);

    // 4) softmax + query mask
    softmax_kernel<<<(B * L) / 8, 256>>>(qmask, out);
}